// round 3
// baseline (speedup 1.0000x reference)
#include <cuda_runtime.h>

#define N_NODES 10000
#define KK1 10
#define KK2 25
#define DIM 64
#define OUTD 128
#define NGRAPH 64

typedef unsigned long long ull;

__device__ float g_XR[N_NODES * 256];   // per node0: [a01(128) | mean_relu_a12(128)]
__device__ float g_Seg[NGRAPH * OUTD];

__device__ __forceinline__ void ffma2(ull& acc, ull a, ull b) {
    asm("fma.rn.f32x2 %0, %1, %2, %0;" : "+l"(acc) : "l"(a), "l"(b));
}
__device__ __forceinline__ float f2sum(ull v) {
    return __uint_as_float((unsigned)v) + __uint_as_float((unsigned)(v >> 32));
}

#define W0T_LD 132              // padded row stride (floats) -> conflict-free LDS.128
#define XS_NODE 1408            // 11 * 128
#define XS_BUF  2816            // 2 nodes

// ---------------------------------------------------------------------------
// Kernel A: fused level-0 pipeline, FFMA2 GEMM, double-buffered Xs,
// ONE __syncthreads per iteration (P1 -> sync -> GEMM, buffers alternate).
// ---------------------------------------------------------------------------
extern "C" __global__ void __launch_bounds__(256, 2)
kA(const float* __restrict__ h0, const float* __restrict__ h1,
   const float* __restrict__ h2, const float* __restrict__ w0,
   const float* __restrict__ b0)
{
    extern __shared__ float sm[];
    float* w0Ts = sm;                       // [128 cols][132] = 16896 floats
    float* b0s  = sm + 16896;               // 128
    float* Xs   = sm + 17024;               // 2 buffers x 2816 floats

    const int t = threadIdx.x;

    // Zero segment accumulator (kB runs after kA in stream order).
    if (blockIdx.x < 32)
        g_Seg[blockIdx.x * 256 + t] = 0.f;

    // Stage w0 transposed: w0Ts[col][k] = w0[k][col].
    for (int i = t; i < 4096; i += 256) {
        const int k  = i >> 5;              // 0..127
        const int cq = i & 31;              // float4 group of cols
        const float4 v = __ldg((const float4*)(w0 + k * 128) + cq);
        w0Ts[(cq * 4 + 0) * W0T_LD + k] = v.x;
        w0Ts[(cq * 4 + 1) * W0T_LD + k] = v.y;
        w0Ts[(cq * 4 + 2) * W0T_LD + k] = v.z;
        w0Ts[(cq * 4 + 3) * W0T_LD + k] = v.w;
    }
    if (t < 128) b0s[t] = b0[t];
    __syncthreads();

    const int gnode = t >> 7;               // GEMM: node 0/1
    const int gcol  = t & 127;              // GEMM: output column

    int bufsel = 0;
    for (int np = blockIdx.x * 2; np < N_NODES; np += gridDim.x * 2) {
        float* Xb = Xs + bufsel * XS_BUF;

        // ---- P1: fill Xb (all tasks independent; no internal sync) ----
        #pragma unroll
        for (int pass = 0; pass < 2; ++pass) {
            const int task = t + pass * 256;
            if (task < 320) {
                // h2 mean + h1 row: (node, j, c4)
                const int node = task / 160;
                const int rem  = task - node * 160;
                const int j    = rem >> 4;
                const int c4   = rem & 15;
                const int base = (np + node) * KK1 + j;
                const float4* p = (const float4*)(h2 + base * (KK2 * DIM)) + c4;
                float4 s0 = make_float4(0.f, 0.f, 0.f, 0.f);
                float4 s1 = make_float4(0.f, 0.f, 0.f, 0.f);
                #pragma unroll
                for (int k = 0; k < 24; k += 2) {
                    const float4 a = __ldg(p + k * 16);
                    const float4 b = __ldg(p + (k + 1) * 16);
                    s0.x += a.x; s0.y += a.y; s0.z += a.z; s0.w += a.w;
                    s1.x += b.x; s1.y += b.y; s1.z += b.z; s1.w += b.w;
                }
                const float4 a = __ldg(p + 24 * 16);
                s0.x += a.x; s0.y += a.y; s0.z += a.z; s0.w += a.w;
                float4* xrow = (float4*)(Xb + node * XS_NODE + j * 128);
                xrow[16 + c4] = make_float4((s0.x + s1.x) * 0.04f,
                                            (s0.y + s1.y) * 0.04f,
                                            (s0.z + s1.z) * 0.04f,
                                            (s0.w + s1.w) * 0.04f);
                xrow[c4] = __ldg((const float4*)(h1 + base * DIM) + c4);
            } else if (task < 352) {
                // h0 -> row 10 cols 0..63
                const int idx = task - 320;
                const int node = idx >> 4, c4 = idx & 15;
                ((float4*)(Xb + node * XS_NODE + 10 * 128))[c4] =
                    __ldg((const float4*)(h0 + (np + node) * DIM) + c4);
            } else if (task < 384) {
                // mean of h1 rows (re-read global) -> row 10 cols 64..127
                const int idx = task - 352;
                const int node = idx >> 4, c4 = idx & 15;
                const float4* p = (const float4*)(h1 + (np + node) * KK1 * DIM) + c4;
                float4 s = make_float4(0.f, 0.f, 0.f, 0.f);
                #pragma unroll
                for (int j = 0; j < KK1; ++j) {
                    const float4 v = __ldg(p + j * 16);
                    s.x += v.x; s.y += v.y; s.z += v.z; s.w += v.w;
                }
                ((float4*)(Xb + node * XS_NODE + 10 * 128))[16 + c4] =
                    make_float4(s.x * 0.1f, s.y * 0.1f, s.z * 0.1f, s.w * 0.1f);
            }
        }
        __syncthreads();   // the ONLY barrier in the loop

        // ---- GEMM: Y(11x128) = relu(X @ w0 + b0), FFMA2 ----
        const float* X = Xb + gnode * XS_NODE;
        const ulonglong2* wrow = (const ulonglong2*)(w0Ts + gcol * W0T_LD);

        ull acc[11];
        #pragma unroll
        for (int r = 0; r < 11; ++r) acc[r] = 0ull;

        #pragma unroll 4
        for (int kq = 0; kq < 32; ++kq) {
            const ulonglong2 w = wrow[kq];
            #pragma unroll
            for (int r = 0; r < 11; ++r) {
                const ulonglong2 x = *(const ulonglong2*)(X + r * 128 + kq * 4);
                ffma2(acc[r], x.x, w.x);
                ffma2(acc[r], x.y, w.y);
            }
        }

        const float bb = b0s[gcol];
        float ym = 0.f;
        #pragma unroll
        for (int r = 0; r < KK1; ++r) ym += fmaxf(f2sum(acc[r]) + bb, 0.f);
        const float a01 = fmaxf(f2sum(acc[10]) + bb, 0.f);

        g_XR[(np + gnode) * 256 + gcol]       = a01;
        g_XR[(np + gnode) * 256 + 128 + gcol] = ym * 0.1f;

        bufsel ^= 1;   // next P1 writes the other buffer -> no trailing sync
    }
}

// ---------------------------------------------------------------------------
// Kernel B: out = relu(XR @ w1 + b1) + segment-sum atomics. FFMA2,
// transposed w1 column-slice in smem (64 cols/block), 3 blocks/SM.
// ---------------------------------------------------------------------------
#define W1T_LD 260
extern "C" __global__ void __launch_bounds__(256, 3)
kB(const float* __restrict__ w1, const float* __restrict__ b1,
   const int* __restrict__ gid)
{
    extern __shared__ float sm[];
    float* w1Ts = sm;                 // [64 cols][260] = 16640 floats
    float* xs   = sm + 16640;         // 4 rows x 256

    const int t     = threadIdx.x;
    const int half  = blockIdx.x & 1;
    const int bslot = blockIdx.x >> 1;
    const int cl    = t & 63;
    const int c     = cl + half * 64;
    const int rsub  = t >> 6;

    // Stage w1 slice transposed: w1Ts[cl][k] = w1[k][half*64 + cl].
    for (int i = t; i < 4096; i += 256) {
        const int k  = i >> 4;        // 0..255
        const int cq = i & 15;
        const float4 v = __ldg((const float4*)(w1 + k * 128 + half * 64) + cq);
        w1Ts[(cq * 4 + 0) * W1T_LD + k] = v.x;
        w1Ts[(cq * 4 + 1) * W1T_LD + k] = v.y;
        w1Ts[(cq * 4 + 2) * W1T_LD + k] = v.z;
        w1Ts[(cq * 4 + 3) * W1T_LD + k] = v.w;
    }
    __syncthreads();

    const int nblocks = gridDim.x >> 1;
    const int per  = (N_NODES + nblocks - 1) / nblocks;
    const int r0   = bslot * per;
    const int rend = min(r0 + per, N_NODES);
    const float bb = __ldg(b1 + c);
    const ulonglong2* wr = (const ulonglong2*)(w1Ts + cl * W1T_LD);

    for (int rb = r0; rb < rend; rb += 4) {
        {
            const int rr = rb + rsub;
            const int q  = t & 63;
            ((float4*)(xs + rsub * 256))[q] = (rr < rend)
                ? __ldg((const float4*)(g_XR + rr * 256) + q)
                : make_float4(0.f, 0.f, 0.f, 0.f);
        }
        __syncthreads();

        const int row = rb + rsub;
        if (row < rend) {
            const float* x = xs + rsub * 256;
            ull a0 = 0ull, a1 = 0ull;
            #pragma unroll 8
            for (int kq = 0; kq < 64; ++kq) {
                const ulonglong2 w  = wr[kq];
                const ulonglong2 xv = *(const ulonglong2*)(x + kq * 4);
                ffma2(a0, xv.x, w.x);
                ffma2(a1, xv.y, w.y);
            }
            const float y = fmaxf(f2sum(a0) + f2sum(a1) + bb, 0.f);
            atomicAdd(&g_Seg[__ldg(gid + row) * OUTD + c], y);
        }
        __syncthreads();
    }
}

// ---------------------------------------------------------------------------
// Kernel C: readout MLP, one block per graph.
// ---------------------------------------------------------------------------
extern "C" __global__ void __launch_bounds__(64, 8)
kC(const float* __restrict__ wr1, const float* __restrict__ br1,
   const float* __restrict__ wr2, const float* __restrict__ br2,
   const float* __restrict__ wr3, const float* __restrict__ br3,
   float* __restrict__ out)
{
    __shared__ float r1s[35];
    __shared__ float r2s[35];
    const int g = blockIdx.x, t = threadIdx.x;
    const float SC = 1.0507009873554805f;
    const float AL = 1.6732632423543772f;

    if (t < 35) {
        float acc = br1[t];
        #pragma unroll 4
        for (int k = 0; k < OUTD; ++k)
            acc = fmaf(g_Seg[g * OUTD + k], wr1[k * 35 + t], acc);
        r1s[t] = (acc > 0.f) ? SC * acc : SC * AL * (expf(acc) - 1.f);
    }
    __syncthreads();

    if (t < 35) {
        float acc = br2[t];
        #pragma unroll
        for (int k = 0; k < 35; ++k)
            acc = fmaf(r1s[k], wr2[k * 35 + t], acc);
        r2s[t] = (acc > 0.f) ? SC * acc : SC * AL * (expf(acc) - 1.f);
    }
    __syncthreads();

    if (t == 0) {
        float acc = br3[0];
        #pragma unroll
        for (int k = 0; k < 35; ++k)
            acc = fmaf(r2s[k], wr3[k], acc);
        out[g] = acc;
    }
}

// ---------------------------------------------------------------------------
extern "C" void kernel_launch(void* const* d_in, const int* in_sizes, int n_in,
                              void* d_out, int out_size)
{
    const float* h0  = (const float*)d_in[0];
    const float* h1  = (const float*)d_in[1];
    const float* h2  = (const float*)d_in[2];
    const float* w0  = (const float*)d_in[3];
    const float* b0  = (const float*)d_in[4];
    const float* w1  = (const float*)d_in[5];
    const float* b1  = (const float*)d_in[6];
    const float* wr1 = (const float*)d_in[7];
    const float* br1 = (const float*)d_in[8];
    const float* wr2 = (const float*)d_in[9];
    const float* br2 = (const float*)d_in[10];
    const float* wr3 = (const float*)d_in[11];
    const float* br3 = (const float*)d_in[12];
    const int*   gid = (const int*)d_in[13];

    const int smA = (16896 + 128 + 2 * XS_BUF) * 4;   // 90,752 B
    const int smB = (16640 + 1024) * 4;               // 70,656 B
    cudaFuncSetAttribute(kA, cudaFuncAttributeMaxDynamicSharedMemorySize, smA);
    cudaFuncSetAttribute(kB, cudaFuncAttributeMaxDynamicSharedMemorySize, smB);

    kA<<<296, 256, smA>>>(h0, h1, h2, w0, b0);
    kB<<<444, 256, smB>>>(w1, b1, gid);
    kC<<<NGRAPH, 64>>>(wr1, br1, wr2, br2, wr3, br3, (float*)d_out);
}

// round 4
// speedup vs baseline: 1.2597x; 1.2597x over previous
#include <cuda_runtime.h>

#define N_NODES 10000
#define KK1 10
#define KK2 25
#define DIM 64
#define OUTD 128
#define NGRAPH 64
#define NSLOT 4

typedef unsigned long long ull;

__device__ float g_XR[N_NODES * 256];   // per node0: [a01(128) | mean_relu_a12(128)]
__device__ float g_Seg[NGRAPH * OUTD];

__device__ __forceinline__ void ffma2(ull& acc, ull a, ull b) {
    asm("fma.rn.f32x2 %0, %1, %2, %0;" : "+l"(acc) : "l"(a), "l"(b));
}
__device__ __forceinline__ float f2sum(ull v) {
    return __uint_as_float((unsigned)v) + __uint_as_float((unsigned)(v >> 32));
}
__device__ __forceinline__ unsigned smem_u32(const void* p) {
    unsigned a;
    asm("{ .reg .u64 t; cvta.to.shared.u64 t, %1; cvt.u32.u64 %0, t; }"
        : "=r"(a) : "l"(p));
    return a;
}
__device__ __forceinline__ void mbar_init(unsigned addr, unsigned cnt) {
    asm volatile("mbarrier.init.shared.b64 [%0], %1;" :: "r"(addr), "r"(cnt) : "memory");
}
__device__ __forceinline__ void mbar_arrive(unsigned addr) {
    asm volatile("mbarrier.arrive.release.cta.shared::cta.b64 _, [%0];" :: "r"(addr) : "memory");
}
__device__ __forceinline__ void mbar_wait(unsigned addr, int phase) {
    asm volatile(
        "{\n\t.reg .pred P;\n\t"
        "WL_%=:\n\t"
        "mbarrier.try_wait.parity.acquire.cta.shared::cta.b64 P, [%0], %1, 0x989680;\n\t"
        "@P bra.uni WD_%=;\n\t"
        "bra.uni WL_%=;\n\t"
        "WD_%=:\n\t}"
        :: "r"(addr), "r"(phase) : "memory");
}

#define W0T_LD 132              // odd-float4 stride -> conflict-free LDS.128
#define XS_NODE 1408            // 11 * 128
#define XS_PAIR 2816            // 2 nodes

// ---------------------------------------------------------------------------
// Kernel A: warp-specialized. Warps 0-7 (t<256): GEMM consumers.
// Warps 8-15 (t>=256): h2/h1/h0 streaming producers. 4-slot smem ring,
// mbarrier full/empty handoff. 1 block/SM, grid=148.
// ---------------------------------------------------------------------------
extern "C" __global__ void __launch_bounds__(512, 1)
kA(const float* __restrict__ h0, const float* __restrict__ h1,
   const float* __restrict__ h2, const float* __restrict__ w0,
   const float* __restrict__ b0)
{
    extern __shared__ float sm[];
    // layout: [0:32) mbarriers (full[s]=s*16, empty[s]=s*16+8 bytes)
    float* w0Ts = sm + 32;                 // [128 cols][132]
    float* b0s  = w0Ts + 16896;            // 128
    float* ring = b0s + 128;               // NSLOT * 2816

    const int t = threadIdx.x;
    const unsigned mb = smem_u32(sm);

    if (t == 0) {
        #pragma unroll
        for (int s = 0; s < NSLOT; ++s) {
            mbar_init(mb + s * 16, 256);       // full: 256 producer arrivals
            mbar_init(mb + s * 16 + 8, 256);   // empty: 256 consumer arrivals
        }
    }

    // Zero segment accumulator (kB runs after kA in stream order).
    if (blockIdx.x < 16)
        g_Seg[blockIdx.x * 512 + t] = 0.f;

    // Stage w0 transposed: w0Ts[col][k] = w0[k][col].
    for (int i = t; i < 4096; i += 512) {
        const int k  = i >> 5;
        const int cq = i & 31;
        const float4 v = __ldg((const float4*)(w0 + k * 128) + cq);
        w0Ts[(cq * 4 + 0) * W0T_LD + k] = v.x;
        w0Ts[(cq * 4 + 1) * W0T_LD + k] = v.y;
        w0Ts[(cq * 4 + 2) * W0T_LD + k] = v.z;
        w0Ts[(cq * 4 + 3) * W0T_LD + k] = v.w;
    }
    if (t < 128) b0s[t] = b0[t];
    __syncthreads();

    if (t >= 256) {
        // ===================== PRODUCER =====================
        const int p = t - 256;
        int slot = 0, ph = 1;   // empty barriers pass immediately on round 1
        for (int np = blockIdx.x * 2; np < N_NODES; np += gridDim.x * 2) {
            mbar_wait(mb + slot * 16 + 8, ph);
            float* Xb = ring + slot * XS_PAIR;

            #pragma unroll
            for (int pass = 0; pass < 2; ++pass) {
                const int task = p + pass * 256;
                if (task < 320) {
                    const int node = task / 160;
                    const int rem  = task - node * 160;
                    const int j    = rem >> 4;
                    const int c4   = rem & 15;
                    const int base = (np + node) * KK1 + j;
                    const float4* q = (const float4*)(h2 + base * (KK2 * DIM)) + c4;
                    float4 s0 = make_float4(0.f, 0.f, 0.f, 0.f);
                    float4 s1 = make_float4(0.f, 0.f, 0.f, 0.f);
                    #pragma unroll
                    for (int k = 0; k < 24; k += 2) {
                        const float4 a = __ldg(q + k * 16);
                        const float4 b = __ldg(q + (k + 1) * 16);
                        s0.x += a.x; s0.y += a.y; s0.z += a.z; s0.w += a.w;
                        s1.x += b.x; s1.y += b.y; s1.z += b.z; s1.w += b.w;
                    }
                    const float4 a = __ldg(q + 24 * 16);
                    s0.x += a.x; s0.y += a.y; s0.z += a.z; s0.w += a.w;
                    float4* xrow = (float4*)(Xb + node * XS_NODE + j * 128);
                    xrow[16 + c4] = make_float4((s0.x + s1.x) * 0.04f,
                                                (s0.y + s1.y) * 0.04f,
                                                (s0.z + s1.z) * 0.04f,
                                                (s0.w + s1.w) * 0.04f);
                    xrow[c4] = __ldg((const float4*)(h1 + base * DIM) + c4);
                } else if (task < 352) {
                    const int idx = task - 320;
                    const int node = idx >> 4, c4 = idx & 15;
                    ((float4*)(Xb + node * XS_NODE + 10 * 128))[c4] =
                        __ldg((const float4*)(h0 + (np + node) * DIM) + c4);
                } else if (task < 384) {
                    const int idx = task - 352;
                    const int node = idx >> 4, c4 = idx & 15;
                    const float4* q = (const float4*)(h1 + (np + node) * KK1 * DIM) + c4;
                    float4 s = make_float4(0.f, 0.f, 0.f, 0.f);
                    #pragma unroll
                    for (int j = 0; j < KK1; ++j) {
                        const float4 v = __ldg(q + j * 16);
                        s.x += v.x; s.y += v.y; s.z += v.z; s.w += v.w;
                    }
                    ((float4*)(Xb + node * XS_NODE + 10 * 128))[16 + c4] =
                        make_float4(s.x * 0.1f, s.y * 0.1f, s.z * 0.1f, s.w * 0.1f);
                }
            }
            mbar_arrive(mb + slot * 16);            // full
            if (++slot == NSLOT) { slot = 0; ph ^= 1; }
        }
    } else {
        // ===================== CONSUMER =====================
        const int gnode = t >> 7;
        const int gcol  = t & 127;
        const ulonglong2* wrow = (const ulonglong2*)(w0Ts + gcol * W0T_LD);
        const float bb = b0s[gcol];

        int slot = 0, ph = 0;
        for (int np = blockIdx.x * 2; np < N_NODES; np += gridDim.x * 2) {
            mbar_wait(mb + slot * 16, ph);          // full
            const float* X = ring + slot * XS_PAIR + gnode * XS_NODE;

            ull acc[11];
            #pragma unroll
            for (int r = 0; r < 11; ++r) acc[r] = 0ull;

            #pragma unroll 4
            for (int kq = 0; kq < 32; ++kq) {
                const ulonglong2 w = wrow[kq];
                #pragma unroll
                for (int r = 0; r < 11; ++r) {
                    const ulonglong2 x = *(const ulonglong2*)(X + r * 128 + kq * 4);
                    ffma2(acc[r], x.x, w.x);
                    ffma2(acc[r], x.y, w.y);
                }
            }

            float ym = 0.f;
            #pragma unroll
            for (int r = 0; r < KK1; ++r) ym += fmaxf(f2sum(acc[r]) + bb, 0.f);
            const float a01 = fmaxf(f2sum(acc[10]) + bb, 0.f);

            g_XR[(np + gnode) * 256 + gcol]       = a01;
            g_XR[(np + gnode) * 256 + 128 + gcol] = ym * 0.1f;

            mbar_arrive(mb + slot * 16 + 8);        // empty
            if (++slot == NSLOT) { slot = 0; ph ^= 1; }
        }
    }
}

// ---------------------------------------------------------------------------
// Kernel B: barrier-free. Warp-per-2-rows: x via broadcast LDG (L2),
// w1 64-col transposed slice in smem, 2 cols x 2 rows per lane (FFMA2),
// sorted-gid atomic coalescing.
// ---------------------------------------------------------------------------
#define W1T_LD 260
extern "C" __global__ void __launch_bounds__(256, 3)
kB(const float* __restrict__ w1, const float* __restrict__ b1,
   const int* __restrict__ gid)
{
    extern __shared__ float sm[];     // [64 cols][260]
    const int t     = threadIdx.x;
    const int half  = blockIdx.x & 1;
    const int bslot = blockIdx.x >> 1;

    for (int i = t; i < 4096; i += 256) {
        const int k  = i >> 4;
        const int cq = i & 15;
        const float4 v = __ldg((const float4*)(w1 + k * 128 + half * 64) + cq);
        sm[(cq * 4 + 0) * W1T_LD + k] = v.x;
        sm[(cq * 4 + 1) * W1T_LD + k] = v.y;
        sm[(cq * 4 + 2) * W1T_LD + k] = v.z;
        sm[(cq * 4 + 3) * W1T_LD + k] = v.w;
    }
    __syncthreads();

    const int lane = t & 31;
    const int wid  = t >> 5;
    const int c0   = half * 64 + lane;
    const int c1   = c0 + 32;
    const float bb0 = __ldg(b1 + c0);
    const float bb1 = __ldg(b1 + c1);
    const ulonglong2* wp0 = (const ulonglong2*)(sm + lane * W1T_LD);
    const ulonglong2* wp1 = (const ulonglong2*)(sm + (lane + 32) * W1T_LD);

    const int NW   = (gridDim.x >> 1) * 8;   // warps per half
    const int wgid = bslot * 8 + wid;

    for (int r0 = wgid * 2; r0 < N_NODES; r0 += NW * 2) {
        const int r1 = r0 + 1;
        const ulonglong2* xa = (const ulonglong2*)(g_XR + r0 * 256);
        const ulonglong2* xb = (const ulonglong2*)(g_XR + r1 * 256);

        ull aA0 = 0, aA1 = 0, aB0 = 0, aB1 = 0;
        ull bA0 = 0, bA1 = 0, bB0 = 0, bB1 = 0;
        #pragma unroll 4
        for (int kq = 0; kq < 64; ++kq) {
            const ulonglong2 w0v = wp0[kq];
            const ulonglong2 w1v = wp1[kq];
            const ulonglong2 x0  = __ldg(xa + kq);
            const ulonglong2 x1  = __ldg(xb + kq);
            ffma2(aA0, x0.x, w0v.x); ffma2(aA1, x0.y, w0v.y);
            ffma2(aB0, x0.x, w1v.x); ffma2(aB1, x0.y, w1v.y);
            ffma2(bA0, x1.x, w0v.x); ffma2(bA1, x1.y, w0v.y);
            ffma2(bB0, x1.x, w1v.x); ffma2(bB1, x1.y, w1v.y);
        }
        const float yA0 = fmaxf(f2sum(aA0) + f2sum(aA1) + bb0, 0.f);
        const float yA1 = fmaxf(f2sum(aB0) + f2sum(aB1) + bb1, 0.f);
        const float yB0 = fmaxf(f2sum(bA0) + f2sum(bA1) + bb0, 0.f);
        const float yB1 = fmaxf(f2sum(bB0) + f2sum(bB1) + bb1, 0.f);

        const int g0 = __ldg(gid + r0);
        const int g1 = __ldg(gid + r1);
        if (g0 == g1) {
            atomicAdd(&g_Seg[g0 * OUTD + c0], yA0 + yB0);
            atomicAdd(&g_Seg[g0 * OUTD + c1], yA1 + yB1);
        } else {
            atomicAdd(&g_Seg[g0 * OUTD + c0], yA0);
            atomicAdd(&g_Seg[g0 * OUTD + c1], yA1);
            atomicAdd(&g_Seg[g1 * OUTD + c0], yB0);
            atomicAdd(&g_Seg[g1 * OUTD + c1], yB1);
        }
    }
}

// ---------------------------------------------------------------------------
// Kernel C: readout MLP, one block per graph.
// ---------------------------------------------------------------------------
extern "C" __global__ void __launch_bounds__(64, 8)
kC(const float* __restrict__ wr1, const float* __restrict__ br1,
   const float* __restrict__ wr2, const float* __restrict__ br2,
   const float* __restrict__ wr3, const float* __restrict__ br3,
   float* __restrict__ out)
{
    __shared__ float r1s[35];
    __shared__ float r2s[35];
    const int g = blockIdx.x, t = threadIdx.x;
    const float SC = 1.0507009873554805f;
    const float AL = 1.6732632423543772f;

    if (t < 35) {
        float acc = br1[t];
        #pragma unroll 4
        for (int k = 0; k < OUTD; ++k)
            acc = fmaf(g_Seg[g * OUTD + k], wr1[k * 35 + t], acc);
        r1s[t] = (acc > 0.f) ? SC * acc : SC * AL * (expf(acc) - 1.f);
    }
    __syncthreads();

    if (t < 35) {
        float acc = br2[t];
        #pragma unroll
        for (int k = 0; k < 35; ++k)
            acc = fmaf(r1s[k], wr2[k * 35 + t], acc);
        r2s[t] = (acc > 0.f) ? SC * acc : SC * AL * (expf(acc) - 1.f);
    }
    __syncthreads();

    if (t == 0) {
        float acc = br3[0];
        #pragma unroll
        for (int k = 0; k < 35; ++k)
            acc = fmaf(r2s[k], wr3[k], acc);
        out[g] = acc;
    }
}

// ---------------------------------------------------------------------------
extern "C" void kernel_launch(void* const* d_in, const int* in_sizes, int n_in,
                              void* d_out, int out_size)
{
    const float* h0  = (const float*)d_in[0];
    const float* h1  = (const float*)d_in[1];
    const float* h2  = (const float*)d_in[2];
    const float* w0  = (const float*)d_in[3];
    const float* b0  = (const float*)d_in[4];
    const float* w1  = (const float*)d_in[5];
    const float* b1  = (const float*)d_in[6];
    const float* wr1 = (const float*)d_in[7];
    const float* br1 = (const float*)d_in[8];
    const float* wr2 = (const float*)d_in[9];
    const float* br2 = (const float*)d_in[10];
    const float* wr3 = (const float*)d_in[11];
    const float* br3 = (const float*)d_in[12];
    const int*   gid = (const int*)d_in[13];

    const int smA = (32 + 16896 + 128 + NSLOT * XS_PAIR) * 4;   // 113,280 B
    const int smB = (64 * W1T_LD) * 4;                          // 66,560 B
    cudaFuncSetAttribute(kA, cudaFuncAttributeMaxDynamicSharedMemorySize, smA);
    cudaFuncSetAttribute(kB, cudaFuncAttributeMaxDynamicSharedMemorySize, smB);

    kA<<<148, 512, smA>>>(h0, h1, h2, w0, b0);
    kB<<<444, 256, smB>>>(w1, b1, gid);
    kC<<<NGRAPH, 64>>>(wr1, br1, wr2, br2, wr3, br3, (float*)d_out);
}

// round 5
// speedup vs baseline: 1.2868x; 1.0215x over previous
#include <cuda_runtime.h>

#define N_NODES 10000
#define KK1 10
#define KK2 25
#define DIM 64
#define OUTD 128
#define NGRAPH 64
#define NSLOT 4

typedef unsigned long long ull;

__device__ float g_XR[N_NODES * 256];   // per node0: [a01(128) | mean_relu_a12(128)]
__device__ float g_Seg[NGRAPH * OUTD];

__device__ __forceinline__ void ffma2(ull& acc, ull a, ull b) {
    asm("fma.rn.f32x2 %0, %1, %2, %0;" : "+l"(acc) : "l"(a), "l"(b));
}
__device__ __forceinline__ float f2sum(ull v) {
    return __uint_as_float((unsigned)v) + __uint_as_float((unsigned)(v >> 32));
}
__device__ __forceinline__ unsigned smem_u32(const void* p) {
    unsigned a;
    asm("{ .reg .u64 t; cvta.to.shared.u64 t, %1; cvt.u32.u64 %0, t; }"
        : "=r"(a) : "l"(p));
    return a;
}
__device__ __forceinline__ void mbar_init(unsigned addr, unsigned cnt) {
    asm volatile("mbarrier.init.shared.b64 [%0], %1;" :: "r"(addr), "r"(cnt) : "memory");
}
__device__ __forceinline__ void mbar_arrive(unsigned addr) {
    asm volatile("mbarrier.arrive.release.cta.shared::cta.b64 _, [%0];" :: "r"(addr) : "memory");
}
__device__ __forceinline__ void mbar_wait(unsigned addr, int phase) {
    asm volatile(
        "{\n\t.reg .pred P;\n\t"
        "WL_%=:\n\t"
        "mbarrier.try_wait.parity.acquire.cta.shared::cta.b64 P, [%0], %1, 0x989680;\n\t"
        "@P bra.uni WD_%=;\n\t"
        "bra.uni WL_%=;\n\t"
        "WD_%=:\n\t}"
        :: "r"(addr), "r"(phase) : "memory");
}

#define W0T_LD 132              // 4*odd stride -> conflict-free LDS.128
#define XS_NODE 1408            // 11 * 128
#define XS_PAIR 2816            // 2 nodes

// ---------------------------------------------------------------------------
// Kernel A: warp-specialized, 384 threads.
//   warps 0-3  (t <128): GEMM consumers, 2 columns per thread.
//   warps 4-11 (t>=128): h2/h1/h0 streaming producers (higher wid = priority).
// 4-slot smem ring, mbarrier full/empty handoff. 1 block/SM, grid=148.
// ---------------------------------------------------------------------------
extern "C" __global__ void __launch_bounds__(384, 1)
kA(const float* __restrict__ h0, const float* __restrict__ h1,
   const float* __restrict__ h2, const float* __restrict__ w0,
   const float* __restrict__ b0)
{
    extern __shared__ float sm[];
    // [0:32) mbarriers (full[s]=s*16, empty[s]=s*16+8 bytes)
    float* w0Ts = sm + 8;                  // [128 cols][132]
    float* b0s  = w0Ts + 16896;            // 128
    float* ring = b0s + 128;               // NSLOT * 2816

    const int t = threadIdx.x;
    const unsigned mb = smem_u32(sm);

    if (t == 0) {
        #pragma unroll
        for (int s = 0; s < NSLOT; ++s) {
            mbar_init(mb + s * 16, 256);       // full: 256 producer arrivals
            mbar_init(mb + s * 16 + 8, 128);   // empty: 128 consumer arrivals
        }
    }

    // Zero segment accumulator (kB runs after kA in stream order).
    if (blockIdx.x < 22) {
        const int idx = blockIdx.x * 384 + t;
        if (idx < NGRAPH * OUTD) g_Seg[idx] = 0.f;
    }

    // Stage w0 transposed: w0Ts[col][k] = w0[k][col].
    for (int i = t; i < 4096; i += 384) {
        const int k  = i >> 5;
        const int cq = i & 31;
        const float4 v = __ldg((const float4*)(w0 + k * 128) + cq);
        w0Ts[(cq * 4 + 0) * W0T_LD + k] = v.x;
        w0Ts[(cq * 4 + 1) * W0T_LD + k] = v.y;
        w0Ts[(cq * 4 + 2) * W0T_LD + k] = v.z;
        w0Ts[(cq * 4 + 3) * W0T_LD + k] = v.w;
    }
    if (t < 128) b0s[t] = b0[t];
    __syncthreads();

    if (t >= 128) {
        // ===================== PRODUCER =====================
        const int p = t - 128;               // 0..255
        int slot = 0, ph = 1;                // empty passes immediately round 1
        for (int np = blockIdx.x * 2; np < N_NODES; np += gridDim.x * 2) {
            mbar_wait(mb + slot * 16 + 8, ph);
            float* Xb = ring + slot * XS_PAIR;

            #pragma unroll
            for (int pass = 0; pass < 2; ++pass) {
                const int task = p + pass * 256;
                if (task < 320) {
                    const int node = task / 160;
                    const int rem  = task - node * 160;
                    const int j    = rem >> 4;
                    const int c4   = rem & 15;
                    const int base = (np + node) * KK1 + j;
                    const float4* q = (const float4*)(h2 + base * (KK2 * DIM)) + c4;
                    float4 s0 = make_float4(0.f, 0.f, 0.f, 0.f);
                    float4 s1 = make_float4(0.f, 0.f, 0.f, 0.f);
                    #pragma unroll
                    for (int k = 0; k < 24; k += 2) {
                        const float4 a = __ldg(q + k * 16);
                        const float4 b = __ldg(q + (k + 1) * 16);
                        s0.x += a.x; s0.y += a.y; s0.z += a.z; s0.w += a.w;
                        s1.x += b.x; s1.y += b.y; s1.z += b.z; s1.w += b.w;
                    }
                    const float4 a = __ldg(q + 24 * 16);
                    s0.x += a.x; s0.y += a.y; s0.z += a.z; s0.w += a.w;
                    float4* xrow = (float4*)(Xb + node * XS_NODE + j * 128);
                    xrow[16 + c4] = make_float4((s0.x + s1.x) * 0.04f,
                                                (s0.y + s1.y) * 0.04f,
                                                (s0.z + s1.z) * 0.04f,
                                                (s0.w + s1.w) * 0.04f);
                    xrow[c4] = __ldg((const float4*)(h1 + base * DIM) + c4);
                } else if (task < 352) {
                    const int idx = task - 320;
                    const int node = idx >> 4, c4 = idx & 15;
                    ((float4*)(Xb + node * XS_NODE + 10 * 128))[c4] =
                        __ldg((const float4*)(h0 + (np + node) * DIM) + c4);
                } else if (task < 384) {
                    const int idx = task - 352;
                    const int node = idx >> 4, c4 = idx & 15;
                    const float4* q = (const float4*)(h1 + (np + node) * KK1 * DIM) + c4;
                    float4 s = make_float4(0.f, 0.f, 0.f, 0.f);
                    #pragma unroll
                    for (int j = 0; j < KK1; ++j) {
                        const float4 v = __ldg(q + j * 16);
                        s.x += v.x; s.y += v.y; s.z += v.z; s.w += v.w;
                    }
                    ((float4*)(Xb + node * XS_NODE + 10 * 128))[16 + c4] =
                        make_float4(s.x * 0.1f, s.y * 0.1f, s.z * 0.1f, s.w * 0.1f);
                }
            }
            mbar_arrive(mb + slot * 16);            // full
            if (++slot == NSLOT) { slot = 0; ph ^= 1; }
        }
    } else {
        // ===================== CONSUMER (2 cols/thread) =====================
        const int node = t >> 6;                   // 0 or 1
        const int col  = t & 63;                   // owns col and col+64
        const ulonglong2* wpa = (const ulonglong2*)(w0Ts + col * W0T_LD);
        const ulonglong2* wpb = (const ulonglong2*)(w0Ts + (col + 64) * W0T_LD);
        const float bbA = b0s[col];
        const float bbB = b0s[col + 64];

        int slot = 0, ph = 0;
        for (int np = blockIdx.x * 2; np < N_NODES; np += gridDim.x * 2) {
            mbar_wait(mb + slot * 16, ph);          // full
            const float* X = ring + slot * XS_PAIR + node * XS_NODE;

            ull accA[11], accB[11];
            #pragma unroll
            for (int r = 0; r < 11; ++r) { accA[r] = 0ull; accB[r] = 0ull; }

            #pragma unroll 2
            for (int kq = 0; kq < 32; ++kq) {
                const ulonglong2 wa = wpa[kq];
                const ulonglong2 wb = wpb[kq];
                #pragma unroll
                for (int r = 0; r < 11; ++r) {
                    const ulonglong2 x = *(const ulonglong2*)(X + r * 128 + kq * 4);
                    ffma2(accA[r], x.x, wa.x);
                    ffma2(accA[r], x.y, wa.y);
                    ffma2(accB[r], x.x, wb.x);
                    ffma2(accB[r], x.y, wb.y);
                }
            }

            float ymA = 0.f, ymB = 0.f;
            #pragma unroll
            for (int r = 0; r < KK1; ++r) {
                ymA += fmaxf(f2sum(accA[r]) + bbA, 0.f);
                ymB += fmaxf(f2sum(accB[r]) + bbB, 0.f);
            }
            const float a01A = fmaxf(f2sum(accA[10]) + bbA, 0.f);
            const float a01B = fmaxf(f2sum(accB[10]) + bbB, 0.f);

            float* xr = g_XR + (np + node) * 256;
            xr[col]            = a01A;
            xr[col + 64]       = a01B;
            xr[128 + col]      = ymA * 0.1f;
            xr[128 + col + 64] = ymB * 0.1f;

            mbar_arrive(mb + slot * 16 + 8);        // empty
            if (++slot == NSLOT) { slot = 0; ph ^= 1; }
        }
    }
}

// ---------------------------------------------------------------------------
// Kernel B: 1 block/SM, full transposed w1 (130KB) in smem, warp-per-row,
// 4 cols per lane, barrier-free after staging; x rows via broadcast LDG (L2).
// ---------------------------------------------------------------------------
#define W1T_LD 260
extern "C" __global__ void __launch_bounds__(512, 1)
kB(const float* __restrict__ w1, const float* __restrict__ b1,
   const int* __restrict__ gid)
{
    extern __shared__ float sm[];     // [128 cols][260]
    const int t = threadIdx.x;

    // Stage w1 transposed: sm[c][k] = w1[k][c];  w1 is [256][128].
    for (int i = t; i < 8192; i += 512) {
        const int k  = i >> 5;        // 0..255
        const int cq = i & 31;        // float4 group of cols
        const float4 v = __ldg((const float4*)(w1 + k * 128) + cq);
        sm[(cq * 4 + 0) * W1T_LD + k] = v.x;
        sm[(cq * 4 + 1) * W1T_LD + k] = v.y;
        sm[(cq * 4 + 2) * W1T_LD + k] = v.z;
        sm[(cq * 4 + 3) * W1T_LD + k] = v.w;
    }
    __syncthreads();

    const int lane = t & 31;
    const int wid  = t >> 5;
    const ulonglong2* wp0 = (const ulonglong2*)(sm + (lane      ) * W1T_LD);
    const ulonglong2* wp1 = (const ulonglong2*)(sm + (lane + 32 ) * W1T_LD);
    const ulonglong2* wp2 = (const ulonglong2*)(sm + (lane + 64 ) * W1T_LD);
    const ulonglong2* wp3 = (const ulonglong2*)(sm + (lane + 96 ) * W1T_LD);
    const float bb0 = __ldg(b1 + lane);
    const float bb1 = __ldg(b1 + lane + 32);
    const float bb2 = __ldg(b1 + lane + 64);
    const float bb3 = __ldg(b1 + lane + 96);

    const int NW = gridDim.x * 16;
    for (int r = blockIdx.x * 16 + wid; r < N_NODES; r += NW) {
        const ulonglong2* xr = (const ulonglong2*)(g_XR + r * 256);
        ull a0 = 0, a1 = 0, a2 = 0, a3 = 0;
        #pragma unroll 4
        for (int kq = 0; kq < 64; ++kq) {
            const ulonglong2 x  = __ldg(xr + kq);
            const ulonglong2 w0v = wp0[kq];
            const ulonglong2 w1v = wp1[kq];
            const ulonglong2 w2v = wp2[kq];
            const ulonglong2 w3v = wp3[kq];
            ffma2(a0, x.x, w0v.x); ffma2(a0, x.y, w0v.y);
            ffma2(a1, x.x, w1v.x); ffma2(a1, x.y, w1v.y);
            ffma2(a2, x.x, w2v.x); ffma2(a2, x.y, w2v.y);
            ffma2(a3, x.x, w3v.x); ffma2(a3, x.y, w3v.y);
        }
        const float y0 = fmaxf(f2sum(a0) + bb0, 0.f);
        const float y1 = fmaxf(f2sum(a1) + bb1, 0.f);
        const float y2 = fmaxf(f2sum(a2) + bb2, 0.f);
        const float y3 = fmaxf(f2sum(a3) + bb3, 0.f);

        float* seg = g_Seg + __ldg(gid + r) * OUTD;
        atomicAdd(seg + lane,      y0);
        atomicAdd(seg + lane + 32, y1);
        atomicAdd(seg + lane + 64, y2);
        atomicAdd(seg + lane + 96, y3);
    }
}

// ---------------------------------------------------------------------------
// Kernel C: readout MLP, one block per graph.
// ---------------------------------------------------------------------------
extern "C" __global__ void __launch_bounds__(64, 8)
kC(const float* __restrict__ wr1, const float* __restrict__ br1,
   const float* __restrict__ wr2, const float* __restrict__ br2,
   const float* __restrict__ wr3, const float* __restrict__ br3,
   float* __restrict__ out)
{
    __shared__ float r1s[35];
    __shared__ float r2s[35];
    const int g = blockIdx.x, t = threadIdx.x;
    const float SC = 1.0507009873554805f;
    const float AL = 1.6732632423543772f;

    if (t < 35) {
        float acc = br1[t];
        #pragma unroll 4
        for (int k = 0; k < OUTD; ++k)
            acc = fmaf(g_Seg[g * OUTD + k], wr1[k * 35 + t], acc);
        r1s[t] = (acc > 0.f) ? SC * acc : SC * AL * (expf(acc) - 1.f);
    }
    __syncthreads();

    if (t < 35) {
        float acc = br2[t];
        #pragma unroll
        for (int k = 0; k < 35; ++k)
            acc = fmaf(r1s[k], wr2[k * 35 + t], acc);
        r2s[t] = (acc > 0.f) ? SC * acc : SC * AL * (expf(acc) - 1.f);
    }
    __syncthreads();

    if (t == 0) {
        float acc = br3[0];
        #pragma unroll
        for (int k = 0; k < 35; ++k)
            acc = fmaf(r2s[k], wr3[k], acc);
        out[g] = acc;
    }
}

// ---------------------------------------------------------------------------
extern "C" void kernel_launch(void* const* d_in, const int* in_sizes, int n_in,
                              void* d_out, int out_size)
{
    const float* h0  = (const float*)d_in[0];
    const float* h1  = (const float*)d_in[1];
    const float* h2  = (const float*)d_in[2];
    const float* w0  = (const float*)d_in[3];
    const float* b0  = (const float*)d_in[4];
    const float* w1  = (const float*)d_in[5];
    const float* b1  = (const float*)d_in[6];
    const float* wr1 = (const float*)d_in[7];
    const float* br1 = (const float*)d_in[8];
    const float* wr2 = (const float*)d_in[9];
    const float* br2 = (const float*)d_in[10];
    const float* wr3 = (const float*)d_in[11];
    const float* br3 = (const float*)d_in[12];
    const int*   gid = (const int*)d_in[13];

    const int smA = (8 + 16896 + 128 + NSLOT * XS_PAIR) * 4;    // 113,184 B
    const int smB = (128 * W1T_LD) * 4;                         // 133,120 B
    cudaFuncSetAttribute(kA, cudaFuncAttributeMaxDynamicSharedMemorySize, smA);
    cudaFuncSetAttribute(kB, cudaFuncAttributeMaxDynamicSharedMemorySize, smB);

    kA<<<148, 384, smA>>>(h0, h1, h2, w0, b0);
    kB<<<148, 512, smB>>>(w1, b1, gid);
    kC<<<NGRAPH, 64>>>(wr1, br1, wr2, br2, wr3, br3, (float*)d_out);
}